// round 8
// baseline (speedup 1.0000x reference)
#include <cuda_runtime.h>

#define NN 768
#define NA 192
#define DD 128
#define HH 6
#define HD 768
#define MM 96
#define PSZ (HD*NN)
#define SCALE 0.08838834764831845f
#define NB 144
#define NT 512

// ---------------- device scratch ----------------
__device__ float g_p[3*PSZ];          // raw q,k,v projections (pre-LN)
__device__ float g_psum[3*NN*24];     // per (mat,row): 12 chunks x (sum, sumsq)
__device__ float g_att[NN*HD];        // attention output
__device__ float g_part[6*NN*DD];     // o1 split-K partials
__device__ int   g_inv[NN];           // node -> output row
__device__ unsigned int g_count = 0;
__device__ unsigned int g_gen = 0;

// grid-wide barrier: sense-free, generation-relative (graph-replay safe)
__device__ __forceinline__ void gsync(unsigned int base, unsigned int i) {
    __threadfence();
    __syncthreads();
    if (threadIdx.x == 0) {
        unsigned int old = atomicInc(&g_count, NB - 1u);
        if (old == NB - 1u) {
            atomicExch(&g_gen, base + i);
        } else {
            while ((*(volatile unsigned int*)&g_gen - base) < i) { }
            __threadfence();
        }
    }
    __syncthreads();
}

#define DYN_SMEM ((4096 + 12544 + 224 + 224 + 384 + 384)*4 + 96*4)
#define KPITCH 130
#define VPITCH 98
#define SPITCH 98

__global__ void __launch_bounds__(NT) megak(
    const float* __restrict__ agents, const int* __restrict__ agent_ids,
    const float* __restrict__ lanes,  const int* __restrict__ lane_ids,
    const float* __restrict__ Wq, const float* __restrict__ gq, const float* __restrict__ bq,
    const float* __restrict__ Wk, const float* __restrict__ gk, const float* __restrict__ bk,
    const float* __restrict__ Wv, const float* __restrict__ gv, const float* __restrict__ bv,
    const float* __restrict__ Wo1, const float* __restrict__ go1, const float* __restrict__ bo1,
    const float* __restrict__ Wo2, const float* __restrict__ W1,
    const float* __restrict__ gn, const float* __restrict__ bn,
    const float* __restrict__ W2, float* __restrict__ out)
{
    extern __shared__ float sm[];
    int tid = threadIdx.x;
    int bid = blockIdx.x;
    unsigned int base = 0;
    if (tid == 0) base = *(volatile unsigned int*)&g_gen;

    if (bid == 0) {
        for (int t = tid; t < NN; t += NT) {
            if (t < NA) g_inv[agent_ids[t]] = t;
            else        g_inv[NA + lane_ids[t - NA]] = t;
        }
    }

    // ================= stage 1: QKV GEMM (432 jobs of 64x64, K=128) ======
    {
        float* As = sm;                 // 64 x 130
        float* Bs = sm + 64*130;        // 64 x 130
        int tx = tid & 15, ty = tid >> 4;   // ty 0..31
        for (int r = 0; r < 3; r++) {
            int jid = bid + r*NB;
            int mt = jid % 12;
            int nt = jid / 12;
            int sel = nt / 12;
            int nch = nt % 12;
            int m0 = mt*64, w0 = nch*64;
            const float* W  = sel == 0 ? Wq : (sel == 1 ? Wk : Wv);
            const float* Ab = m0 < NA ? agents + m0*DD : lanes + (m0 - NA)*DD;
#pragma unroll
            for (int i = 0; i < 4; i++) {
                int lin = tid + i*NT;
                int row = lin >> 5, c4 = lin & 31;
                float4 v = *(const float4*)&Ab[row*DD + c4*4];
                float* d = &As[row*130 + c4*4];
                d[0]=v.x; d[1]=v.y; d[2]=v.z; d[3]=v.w;
                float4 u = *(const float4*)&W[(w0+row)*DD + c4*4];
                float* e = &Bs[row*130 + c4*4];
                e[0]=u.x; e[1]=u.y; e[2]=u.z; e[3]=u.w;
            }
            __syncthreads();
            float acc[2][4] = {};
#pragma unroll 4
            for (int k2 = 0; k2 < DD; k2 += 2) {
                float2 a[2], b[4];
#pragma unroll
                for (int i = 0; i < 2; i++) a[i] = *(float2*)&As[(ty + 32*i)*130 + k2];
#pragma unroll
                for (int j = 0; j < 4; j++) b[j] = *(float2*)&Bs[(tx + 16*j)*130 + k2];
#pragma unroll
                for (int i = 0; i < 2; i++)
#pragma unroll
                    for (int j = 0; j < 4; j++) {
                        acc[i][j] += a[i].x * b[j].x;
                        acc[i][j] += a[i].y * b[j].y;
                    }
            }
            float* outp = g_p + sel*PSZ;
#pragma unroll
            for (int i = 0; i < 2; i++) {
#pragma unroll
                for (int j = 0; j < 4; j++)
                    outp[(m0 + ty + 32*i)*HD + w0 + tx + 16*j] = acc[i][j];
                float s = 0.f, s2 = 0.f;
#pragma unroll
                for (int j = 0; j < 4; j++) { s += acc[i][j]; s2 += acc[i][j]*acc[i][j]; }
#pragma unroll
                for (int o = 8; o > 0; o >>= 1) {
                    s  += __shfl_xor_sync(0xffffffffu, s,  o);
                    s2 += __shfl_xor_sync(0xffffffffu, s2, o);
                }
                if (tx == 0) {
                    int rr = m0 + ty + 32*i;
                    g_psum[(sel*NN + rr)*24 + nch*2 + 0] = s;
                    g_psum[(sel*NN + rr)*24 + nch*2 + 1] = s2;
                }
            }
            __syncthreads();
        }
    }
    gsync(base, 1);

    // ================= stage 2: fused attention (144 jobs, 1/block) ======
    {
        float* Qs  = sm;                // 32 x 128
        float* Ss  = sm;                // 32 x 98 (aliases Qs)
        float* KV  = sm + 4096;         // K: 96x130 / Vt: 128x98
        float* s_mu = sm + 4096 + 12544;
        float* s_rs = s_mu + 224;
        float* s_g  = s_rs + 224;
        float* s_b  = s_g + 384;
        int*   mem  = (int*)(s_b + 384);

        int rb = bid % 3, head = (bid/3) % HH, gph = bid / (3*HH);
        if (tid < MM)
            mem[tid] = tid < 24 ? agent_ids[gph*24 + tid]
                                : NA + lane_ids[gph*72 + (tid - 24)];
        __syncthreads();
        if (tid < 224) {
            int mat, node;
            if (tid < 32)       { mat = 0; node = mem[rb*32 + tid]; }
            else if (tid < 128) { mat = 1; node = mem[tid - 32]; }
            else                { mat = 2; node = mem[tid - 128]; }
            const float* ps = &g_psum[(mat*NN + node)*24];
            float s = 0.f, s2 = 0.f;
#pragma unroll
            for (int n = 0; n < 12; n++) { s += ps[2*n]; s2 += ps[2*n+1]; }
            float mu = s * (1.f/HD);
            float var = s2 * (1.f/HD) - mu*mu;
            s_mu[tid] = mu;
            s_rs[tid] = rsqrtf(var + 1e-5f);
        }
        // full-coverage affine fill (FIX: previous branch left t=288..383 unset)
        for (int t = tid; t < 384; t += NT) {
            int mat = t >> 7, c = t & 127;
            const float* g  = mat==0 ? gq : (mat==1 ? gk : gv);
            const float* bb = mat==0 ? bq : (mat==1 ? bk : bv);
            s_g[t] = g[head*DD + c];
            s_b[t] = bb[head*DD + c];
        }
        __syncthreads();
        // Q (32 rows) with LN affine
#pragma unroll
        for (int i = 0; i < 2; i++) {
            int lin = tid + i*NT;
            int row = lin >> 5, c4 = lin & 31;
            int node = mem[rb*32 + row];
            float4 v = *(const float4*)&g_p[node*HD + head*DD + c4*4];
            float mu = s_mu[row], rs = s_rs[row];
            float* d = &Qs[row*128 + c4*4];
            d[0] = (v.x-mu)*rs*s_g[c4*4+0] + s_b[c4*4+0];
            d[1] = (v.y-mu)*rs*s_g[c4*4+1] + s_b[c4*4+1];
            d[2] = (v.z-mu)*rs*s_g[c4*4+2] + s_b[c4*4+2];
            d[3] = (v.w-mu)*rs*s_g[c4*4+3] + s_b[c4*4+3];
        }
        // K (96 rows) with LN affine
#pragma unroll
        for (int i = 0; i < 6; i++) {
            int lin = tid + i*NT;
            int row = lin >> 5, c4 = lin & 31;
            int node = mem[row];
            float4 v = *(const float4*)&g_p[PSZ + node*HD + head*DD + c4*4];
            float mu = s_mu[32+row], rs = s_rs[32+row];
            float* d = &KV[row*KPITCH + c4*4];
            d[0] = (v.x-mu)*rs*s_g[128+c4*4+0] + s_b[128+c4*4+0];
            d[1] = (v.y-mu)*rs*s_g[128+c4*4+1] + s_b[128+c4*4+1];
            d[2] = (v.z-mu)*rs*s_g[128+c4*4+2] + s_b[128+c4*4+2];
            d[3] = (v.w-mu)*rs*s_g[128+c4*4+3] + s_b[128+c4*4+3];
        }
        __syncthreads();

        int tx = tid & 15, ty = tid >> 4;   // row ty (0..31), cols tx+16j (j<6)
        float S[6] = {};
#pragma unroll 4
        for (int d2 = 0; d2 < DD; d2 += 2) {
            float2 a0 = *(float2*)&Qs[ty*128 + d2];
#pragma unroll
            for (int j = 0; j < 6; j++) {
                float2 kk = *(float2*)&KV[(tx + 16*j)*KPITCH + d2];
                S[j] += a0.x*kk.x; S[j] += a0.y*kk.y;
            }
        }
        float p[6]; float inv;
        {
            float mx = S[0] * SCALE;
#pragma unroll
            for (int j = 1; j < 6; j++) mx = fmaxf(mx, S[j]*SCALE);
#pragma unroll
            for (int o = 8; o > 0; o >>= 1) mx = fmaxf(mx, __shfl_xor_sync(0xffffffffu, mx, o));
            float sum = 0.f;
#pragma unroll
            for (int j = 0; j < 6; j++) { p[j] = __expf(S[j]*SCALE - mx); sum += p[j]; }
#pragma unroll
            for (int o = 8; o > 0; o >>= 1) sum += __shfl_xor_sync(0xffffffffu, sum, o);
            inv = 1.f / sum;
        }
        __syncthreads();   // Q/K reads done; buffers reusable
#pragma unroll
        for (int j = 0; j < 6; j++)
            Ss[ty*SPITCH + tx + 16*j] = p[j] * inv;
        // V loaded TRANSPOSED (Vt[col][k]) with LN+relu
#pragma unroll
        for (int i = 0; i < 6; i++) {
            int lin = tid + i*NT;
            int row = lin >> 5, c4 = lin & 31;
            int node = mem[row];
            float4 v = *(const float4*)&g_p[2*PSZ + node*HD + head*DD + c4*4];
            float mu = s_mu[128+row], rs = s_rs[128+row];
            KV[(c4*4+0)*VPITCH + row] = fmaxf((v.x-mu)*rs*s_g[256+c4*4+0] + s_b[256+c4*4+0], 0.f);
            KV[(c4*4+1)*VPITCH + row] = fmaxf((v.y-mu)*rs*s_g[256+c4*4+1] + s_b[256+c4*4+1], 0.f);
            KV[(c4*4+2)*VPITCH + row] = fmaxf((v.z-mu)*rs*s_g[256+c4*4+2] + s_b[256+c4*4+2], 0.f);
            KV[(c4*4+3)*VPITCH + row] = fmaxf((v.w-mu)*rs*s_g[256+c4*4+3] + s_b[256+c4*4+3], 0.f);
        }
        __syncthreads();
        float acc[8] = {};
#pragma unroll 4
        for (int k2 = 0; k2 < MM; k2 += 2) {
            float2 s0 = *(float2*)&Ss[ty*SPITCH + k2];
#pragma unroll
            for (int j = 0; j < 8; j++) {
                float2 vv = *(float2*)&KV[(tx + 16*j)*VPITCH + k2];
                acc[j] += s0.x*vv.x; acc[j] += s0.y*vv.y;
            }
        }
        {
            int node = mem[rb*32 + ty];
#pragma unroll
            for (int j = 0; j < 8; j++)
                g_att[node*HD + head*DD + tx + 16*j] = acc[j];
        }
    }
    gsync(base, 2);

    // ================= stage 3: o1 split-K (24 row-tiles x 6 splits) =====
    {
        float* As = sm;             // 32 x 66
        float* Bs = sm + 32*66;     // 128 x 66
        int sp = bid / 24, mt = bid % 24;
        int m0 = mt*32, kb = sp*128;
        int tx = tid & 15, ty = tid >> 4;   // row ty (0..31), cols tx+16j (j<8)
        float acc[8] = {};
        for (int cc = 0; cc < 2; cc++) {
            int k0 = kb + cc*64;
            {
                int row = tid >> 4, c4 = tid & 15;  // 32x16 f4 = 512
                float4 v = *(const float4*)&g_att[(m0+row)*HD + k0 + c4*4];
                float* d = &As[row*66 + c4*4];
                d[0]=v.x; d[1]=v.y; d[2]=v.z; d[3]=v.w;
            }
#pragma unroll
            for (int i = 0; i < 4; i++) {
                int lin = tid + i*NT;
                int row = lin >> 4, c4 = lin & 15;
                float4 v = *(const float4*)&Wo1[row*HD + k0 + c4*4];
                float* d = &Bs[row*66 + c4*4];
                d[0]=v.x; d[1]=v.y; d[2]=v.z; d[3]=v.w;
            }
            __syncthreads();
#pragma unroll 4
            for (int k2 = 0; k2 < 64; k2 += 2) {
                float2 a = *(float2*)&As[ty*66 + k2];
#pragma unroll
                for (int j = 0; j < 8; j++) {
                    float2 b = *(float2*)&Bs[(tx + 16*j)*66 + k2];
                    acc[j] += a.x*b.x; acc[j] += a.y*b.y;
                }
            }
            __syncthreads();
        }
#pragma unroll
        for (int j = 0; j < 8; j++)
            g_part[sp*(NN*DD) + (m0 + ty)*DD + tx + 16*j] = acc[j];
    }
    gsync(base, 3);

    // ====== stage 4: reduce+LN -> mid GEMM+LN -> final GEMM+res+scatter ==
    if (bid < 96) {
        float* nodes_s = sm;                 // 8 x 130
        float* r1_s    = sm + 8*130;         // 8 x 130
        float* h_s     = sm + 2*8*130;       // 8 x 130
        float* Bs      = sm + 3*8*130;       // 128 x 34
        float* red     = sm + 3*8*130 + 128*34;  // 16 x 2
        int m0 = bid*8;
        int row  = tid >> 6;        // 0..7 (row spans 2 warps)
        int lane = tid & 63;
        int wid  = tid >> 5;
        const float* Ab = m0 < NA ? agents + m0*DD : lanes + (m0 - NA)*DD;
        if (tid < 256) {
            int rw = tid >> 5, c4 = tid & 31;
            float4 v = *(const float4*)&Ab[rw*DD + c4*4];
            float* d = &nodes_s[rw*130 + c4*4];
            d[0]=v.x; d[1]=v.y; d[2]=v.z; d[3]=v.w;
            // raw o1 reduce -> r1_s (pre-LN)
            float4 sv = make_float4(0.f,0.f,0.f,0.f);
#pragma unroll
            for (int sp = 0; sp < 6; sp++) {
                float4 u = *(const float4*)&g_part[sp*(NN*DD) + (m0+rw)*DD + c4*4];
                sv.x += u.x; sv.y += u.y; sv.z += u.z; sv.w += u.w;
            }
            float* e = &r1_s[rw*130 + c4*4];
            e[0]=sv.x; e[1]=sv.y; e[2]=sv.z; e[3]=sv.w;
        }
        __syncthreads();
        // LN(go1,bo1)+relu on r1_s (row spans 64 lanes / 2 warps)
        {
            float x0 = r1_s[row*130 + lane];
            float x1 = r1_s[row*130 + lane + 64];
            float s = x0 + x1, s2 = x0*x0 + x1*x1;
#pragma unroll
            for (int o = 16; o > 0; o >>= 1) {
                s  += __shfl_xor_sync(0xffffffffu, s,  o);
                s2 += __shfl_xor_sync(0xffffffffu, s2, o);
            }
            if ((tid & 31) == 0) { red[wid*2] = s; red[wid*2+1] = s2; }
            __syncthreads();
            float ss  = red[(wid^1)*2]   + red[wid*2];
            float ss2 = red[(wid^1)*2+1] + red[wid*2+1];
            float mu = ss*(1.f/DD), var = ss2*(1.f/DD) - mu*mu;
            float rstd = rsqrtf(var + 1e-5f);
            r1_s[row*130 + lane]      = fmaxf((x0-mu)*rstd*go1[lane]    + bo1[lane],    0.f);
            r1_s[row*130 + lane + 64] = fmaxf((x1-mu)*rstd*go1[lane+64] + bo1[lane+64], 0.f);
        }
        __syncthreads();
        // mid GEMM: nodes@W1^T + r1@Wo2^T  (8x128, K=256)
        float acc[2] = {};
        for (int cc = 0; cc < 8; cc++) {
            const float* W = cc < 4 ? W1 : Wo2;
            const float* A = cc < 4 ? nodes_s : r1_s;
            int k0 = (cc & 3) * 32;
#pragma unroll
            for (int i = 0; i < 2; i++) {
                int lin = tid + i*NT;
                int rw = lin >> 3, c4 = lin & 7;
                float4 v = *(const float4*)&W[rw*DD + k0 + c4*4];
                float* d = &Bs[rw*34 + c4*4];
                d[0]=v.x; d[1]=v.y; d[2]=v.z; d[3]=v.w;
            }
            __syncthreads();
#pragma unroll 4
            for (int k2 = 0; k2 < 32; k2 += 2) {
                float2 a = *(float2*)&A[row*130 + k0 + k2];
#pragma unroll
                for (int j = 0; j < 2; j++) {
                    float2 b = *(float2*)&Bs[(lane + 64*j)*34 + k2];
                    acc[j] += a.x*b.x; acc[j] += a.y*b.y;
                }
            }
            __syncthreads();
        }
        // LN(gn,bn)+relu -> h_s
        {
            float s = acc[0] + acc[1], s2 = acc[0]*acc[0] + acc[1]*acc[1];
#pragma unroll
            for (int o = 16; o > 0; o >>= 1) {
                s  += __shfl_xor_sync(0xffffffffu, s,  o);
                s2 += __shfl_xor_sync(0xffffffffu, s2, o);
            }
            if ((tid & 31) == 0) { red[wid*2] = s; red[wid*2+1] = s2; }
            __syncthreads();
            float ss  = red[(wid^1)*2]   + red[wid*2];
            float ss2 = red[(wid^1)*2+1] + red[wid*2+1];
            float mu = ss*(1.f/DD), var = ss2*(1.f/DD) - mu*mu;
            float rstd = rsqrtf(var + 1e-5f);
            h_s[row*130 + lane]      = fmaxf((acc[0]-mu)*rstd*gn[lane]    + bn[lane],    0.f);
            h_s[row*130 + lane + 64] = fmaxf((acc[1]-mu)*rstd*gn[lane+64] + bn[lane+64], 0.f);
        }
        __syncthreads();
        // final GEMM: h @ W2^T (8x128, K=128) + residual + relu + scatter
        float acc2[2] = {};
        for (int cc = 0; cc < 4; cc++) {
            int k0 = cc * 32;
#pragma unroll
            for (int i = 0; i < 2; i++) {
                int lin = tid + i*NT;
                int rw = lin >> 3, c4 = lin & 7;
                float4 v = *(const float4*)&W2[rw*DD + k0 + c4*4];
                float* d = &Bs[rw*34 + c4*4];
                d[0]=v.x; d[1]=v.y; d[2]=v.z; d[3]=v.w;
            }
            __syncthreads();
#pragma unroll 4
            for (int k2 = 0; k2 < 32; k2 += 2) {
                float2 a = *(float2*)&h_s[row*130 + k0 + k2];
#pragma unroll
                for (int j = 0; j < 2; j++) {
                    float2 b = *(float2*)&Bs[(lane + 64*j)*34 + k2];
                    acc2[j] += a.x*b.x; acc2[j] += a.y*b.y;
                }
            }
            __syncthreads();
        }
        int orow = g_inv[m0 + row];
#pragma unroll
        for (int j = 0; j < 2; j++) {
            int c = lane + 64*j;
            out[orow*DD + c] = fmaxf(acc2[j] + nodes_s[row*130 + c], 0.f);
        }
    }
}

// ------------------------------------------------------------------------
extern "C" void kernel_launch(void* const* d_in, const int* in_sizes, int n_in,
                              void* d_out, int out_size) {
    const float* agents    = (const float*)d_in[0];
    const int*   agent_ids = (const int*)  d_in[1];
    const float* lanes     = (const float*)d_in[2];
    const int*   lane_ids  = (const int*)  d_in[3];
    const float* Wq  = (const float*)d_in[4];
    const float* gq  = (const float*)d_in[5];
    const float* bq  = (const float*)d_in[6];
    const float* Wk  = (const float*)d_in[7];
    const float* gk  = (const float*)d_in[8];
    const float* bk  = (const float*)d_in[9];
    const float* Wv  = (const float*)d_in[10];
    const float* gv  = (const float*)d_in[11];
    const float* bv  = (const float*)d_in[12];
    const float* Wo1 = (const float*)d_in[13];
    const float* go1 = (const float*)d_in[14];
    const float* bo1 = (const float*)d_in[15];
    const float* Wo2 = (const float*)d_in[16];
    const float* W1  = (const float*)d_in[17];
    const float* gn  = (const float*)d_in[18];
    const float* bn  = (const float*)d_in[19];
    const float* W2  = (const float*)d_in[20];
    float* out = (float*)d_out;

    cudaFuncSetAttribute(megak, cudaFuncAttributeMaxDynamicSharedMemorySize, DYN_SMEM);

    megak<<<NB, NT, DYN_SMEM>>>(agents, agent_ids, lanes, lane_ids,
                                Wq, gq, bq, Wk, gk, bk, Wv, gv, bv,
                                Wo1, go1, bo1, Wo2, W1, gn, bn, W2, out);
}

// round 9
// speedup vs baseline: 1.1488x; 1.1488x over previous
#include <cuda_runtime.h>
#include <cstdint>

#define NN 768
#define NA 192
#define DD 128
#define HH 6
#define HD 768
#define MM 96
#define PSZ (HD*NN)
#define SCALE 0.08838834764831845f
#define NB 144
#define NT 512

// ---------------- device scratch ----------------
__device__ float g_p[3*PSZ];          // LN'd... raw q,k,v projections (pre-LN)
__device__ float g_psum[3*NN*24];     // per (mat,row): 12 chunks x (sum, sumsq)
__device__ float g_att[NN*HD];        // attention output
__device__ float g_part[6*NN*DD];     // o1 split-K partials
__device__ int   g_inv[NN];           // node -> output row
__device__ unsigned int g_count = 0;
__device__ unsigned int g_gen = 0;

__device__ __forceinline__ void gsync(unsigned int base, unsigned int i) {
    __threadfence();
    __syncthreads();
    if (threadIdx.x == 0) {
        unsigned int old = atomicInc(&g_count, NB - 1u);
        if (old == NB - 1u) {
            atomicExch(&g_gen, base + i);
        } else {
            while ((*(volatile unsigned int*)&g_gen - base) < i) { }
            __threadfence();
        }
    }
    __syncthreads();
}

// tf32 helpers
__device__ __forceinline__ uint32_t f2tf(float x) {
    uint32_t r;
    asm("cvt.rna.tf32.f32 %0, %1;" : "=r"(r) : "f"(x));
    return r;
}
__device__ __forceinline__ void mma_tf32(float* d, const uint32_t* a, const uint32_t* b) {
    asm("mma.sync.aligned.m16n8k8.row.col.f32.tf32.tf32.f32 "
        "{%0,%1,%2,%3}, {%4,%5,%6,%7}, {%8,%9}, {%0,%1,%2,%3};"
        : "+f"(d[0]), "+f"(d[1]), "+f"(d[2]), "+f"(d[3])
        : "r"(a[0]), "r"(a[1]), "r"(a[2]), "r"(a[3]), "r"(b[0]), "r"(b[1]));
}

// stage-1 smem: 4 tiles of 64x132 u32 = 135168 B (the max across stages)
#define DYN_SMEM (4*64*132*4)
#define KPITCH 130
#define VPITCH 98
#define SPITCH 98

__global__ void __launch_bounds__(NT) megak(
    const float* __restrict__ agents, const int* __restrict__ agent_ids,
    const float* __restrict__ lanes,  const int* __restrict__ lane_ids,
    const float* __restrict__ Wq, const float* __restrict__ gq, const float* __restrict__ bq,
    const float* __restrict__ Wk, const float* __restrict__ gk, const float* __restrict__ bk,
    const float* __restrict__ Wv, const float* __restrict__ gv, const float* __restrict__ bv,
    const float* __restrict__ Wo1, const float* __restrict__ go1, const float* __restrict__ bo1,
    const float* __restrict__ Wo2, const float* __restrict__ W1,
    const float* __restrict__ gn, const float* __restrict__ bn,
    const float* __restrict__ W2, float* __restrict__ out)
{
    extern __shared__ float sm[];
    int tid = threadIdx.x;
    int bid = blockIdx.x;
    unsigned int base = 0;
    if (tid == 0) base = *(volatile unsigned int*)&g_gen;

    if (bid == 0) {
        for (int t = tid; t < NN; t += NT) {
            if (t < NA) g_inv[agent_ids[t]] = t;
            else        g_inv[NA + lane_ids[t - NA]] = t;
        }
    }

    // ===== stage 1: QKV GEMM via 3xtf32 mma (144 jobs: 12 mt x 12 nch) ===
    {
        uint32_t* As_hi = (uint32_t*)sm;
        uint32_t* As_lo = As_hi + 64*132;
        uint32_t* Ws_hi = As_lo + 64*132;
        uint32_t* Ws_lo = Ws_hi + 64*132;
        float*    Cs    = (float*)Ws_hi;      // alias, pitch 68, 64x68
        int mt = bid % 12, nch = bid / 12;
        int m0 = mt*64, w0 = nch*64;
        const float* Ab = m0 < NA ? agents + m0*DD : lanes + (m0 - NA)*DD;
        // fill + split A (64x128)
#pragma unroll
        for (int i = 0; i < 4; i++) {
            int lin = tid + i*NT;
            int row = lin >> 5, c4 = lin & 31;
            float4 v = *(const float4*)&Ab[row*DD + c4*4];
            int bse = row*132 + c4*4;
            float xs[4] = {v.x, v.y, v.z, v.w};
#pragma unroll
            for (int c = 0; c < 4; c++) {
                uint32_t hb = f2tf(xs[c]);
                As_hi[bse+c] = hb;
                As_lo[bse+c] = f2tf(xs[c] - __uint_as_float(hb));
            }
        }
        int w = tid >> 5, l = tid & 31;
        int nb = w & 7, mgrp = w >> 3;
        int g = l >> 2, t4 = l & 3;
        for (int sel = 0; sel < 3; sel++) {
            const float* W = sel == 0 ? Wq : (sel == 1 ? Wk : Wv);
            __syncthreads();   // A fill / prev Cs reads complete
#pragma unroll
            for (int i = 0; i < 4; i++) {
                int lin = tid + i*NT;
                int row = lin >> 5, c4 = lin & 31;
                float4 v = *(const float4*)&W[(w0+row)*DD + c4*4];
                int bse = row*132 + c4*4;
                float xs[4] = {v.x, v.y, v.z, v.w};
#pragma unroll
                for (int c = 0; c < 4; c++) {
                    uint32_t hb = f2tf(xs[c]);
                    Ws_hi[bse+c] = hb;
                    Ws_lo[bse+c] = f2tf(xs[c] - __uint_as_float(hb));
                }
            }
            __syncthreads();
            float acc[2][4] = {};
#pragma unroll
            for (int ks = 0; ks < 16; ks++) {
                int k0 = ks*8 + t4;
                int br = (nb*8 + g)*132 + k0;
                uint32_t bh[2] = {Ws_hi[br], Ws_hi[br+4]};
                uint32_t bl[2] = {Ws_lo[br], Ws_lo[br+4]};
#pragma unroll
                for (int tt = 0; tt < 2; tt++) {
                    int ar = ((mgrp*2+tt)*16 + g)*132 + k0;
                    uint32_t ah[4] = {As_hi[ar], As_hi[ar+8*132], As_hi[ar+4], As_hi[ar+8*132+4]};
                    uint32_t al[4] = {As_lo[ar], As_lo[ar+8*132], As_lo[ar+4], As_lo[ar+8*132+4]};
                    mma_tf32(acc[tt], ah, bh);
                    mma_tf32(acc[tt], ah, bl);
                    mma_tf32(acc[tt], al, bh);
                }
            }
            __syncthreads();   // all Ws frag reads done before Cs overwrite
#pragma unroll
            for (int tt = 0; tt < 2; tt++) {
                int r0 = (mgrp*2+tt)*16 + g;
                int col = nb*8 + 2*t4;
                *(float2*)&Cs[r0*68 + col]     = make_float2(acc[tt][0], acc[tt][1]);
                *(float2*)&Cs[(r0+8)*68 + col] = make_float2(acc[tt][2], acc[tt][3]);
            }
            __syncthreads();
            // row stats over this 64-chunk + coalesced store to g_p
            {
                int row = tid >> 3, q = tid & 7;
                float4 v0 = *(float4*)&Cs[row*68 + q*8];
                float4 v1 = *(float4*)&Cs[row*68 + q*8 + 4];
                float s  = v0.x+v0.y+v0.z+v0.w + v1.x+v1.y+v1.z+v1.w;
                float s2 = v0.x*v0.x+v0.y*v0.y+v0.z*v0.z+v0.w*v0.w
                         + v1.x*v1.x+v1.y*v1.y+v1.z*v1.z+v1.w*v1.w;
#pragma unroll
                for (int o = 4; o > 0; o >>= 1) {
                    s  += __shfl_xor_sync(0xffffffffu, s,  o);
                    s2 += __shfl_xor_sync(0xffffffffu, s2, o);
                }
                float* gp = &g_p[sel*PSZ + (m0+row)*HD + w0 + q*8];
                *(float4*)gp = v0;
                *(float4*)(gp+4) = v1;
                if (q == 0) {
                    g_psum[(sel*NN + m0+row)*24 + nch*2 + 0] = s;
                    g_psum[(sel*NN + m0+row)*24 + nch*2 + 1] = s2;
                }
            }
        }
    }
    gsync(base, 1);

    // ================= stage 2: fused attention (144 jobs, 1/block) ======
    {
        float* Qs  = sm;                // 32 x 128
        float* Ss  = sm;                // 32 x 98 (aliases Qs)
        float* KV  = sm + 4096;         // K: 96x130 / Vt: 128x98
        float* s_mu = sm + 4096 + 12544;
        float* s_rs = s_mu + 224;
        float* s_g  = s_rs + 224;
        float* s_b  = s_g + 384;
        int*   mem  = (int*)(s_b + 384);

        int rb = bid % 3, head = (bid/3) % HH, gph = bid / (3*HH);
        if (tid < MM)
            mem[tid] = tid < 24 ? agent_ids[gph*24 + tid]
                                : NA + lane_ids[gph*72 + (tid - 24)];
        __syncthreads();
        if (tid < 224) {
            int mat, node;
            if (tid < 32)       { mat = 0; node = mem[rb*32 + tid]; }
            else if (tid < 128) { mat = 1; node = mem[tid - 32]; }
            else                { mat = 2; node = mem[tid - 128]; }
            const float* ps = &g_psum[(mat*NN + node)*24];
            float s = 0.f, s2 = 0.f;
#pragma unroll
            for (int n = 0; n < 12; n++) { s += ps[2*n]; s2 += ps[2*n+1]; }
            float mu = s * (1.f/HD);
            float var = s2 * (1.f/HD) - mu*mu;
            s_mu[tid] = mu;
            s_rs[tid] = rsqrtf(var + 1e-5f);
        }
        for (int t = tid; t < 384; t += NT) {
            int mat = t >> 7, c = t & 127;
            const float* g  = mat==0 ? gq : (mat==1 ? gk : gv);
            const float* bb = mat==0 ? bq : (mat==1 ? bk : bv);
            s_g[t] = g[head*DD + c];
            s_b[t] = bb[head*DD + c];
        }
        __syncthreads();
#pragma unroll
        for (int i = 0; i < 2; i++) {
            int lin = tid + i*NT;
            int row = lin >> 5, c4 = lin & 31;
            int node = mem[rb*32 + row];
            float4 v = *(const float4*)&g_p[node*HD + head*DD + c4*4];
            float mu = s_mu[row], rs = s_rs[row];
            float* d = &Qs[row*128 + c4*4];
            d[0] = (v.x-mu)*rs*s_g[c4*4+0] + s_b[c4*4+0];
            d[1] = (v.y-mu)*rs*s_g[c4*4+1] + s_b[c4*4+1];
            d[2] = (v.z-mu)*rs*s_g[c4*4+2] + s_b[c4*4+2];
            d[3] = (v.w-mu)*rs*s_g[c4*4+3] + s_b[c4*4+3];
        }
#pragma unroll
        for (int i = 0; i < 6; i++) {
            int lin = tid + i*NT;
            int row = lin >> 5, c4 = lin & 31;
            int node = mem[row];
            float4 v = *(const float4*)&g_p[PSZ + node*HD + head*DD + c4*4];
            float mu = s_mu[32+row], rs = s_rs[32+row];
            float* d = &KV[row*KPITCH + c4*4];
            d[0] = (v.x-mu)*rs*s_g[128+c4*4+0] + s_b[128+c4*4+0];
            d[1] = (v.y-mu)*rs*s_g[128+c4*4+1] + s_b[128+c4*4+1];
            d[2] = (v.z-mu)*rs*s_g[128+c4*4+2] + s_b[128+c4*4+2];
            d[3] = (v.w-mu)*rs*s_g[128+c4*4+3] + s_b[128+c4*4+3];
        }
        __syncthreads();

        int tx = tid & 15, ty = tid >> 4;
        float S[6] = {};
#pragma unroll 4
        for (int d2 = 0; d2 < DD; d2 += 2) {
            float2 a0 = *(float2*)&Qs[ty*128 + d2];
#pragma unroll
            for (int j = 0; j < 6; j++) {
                float2 kk = *(float2*)&KV[(tx + 16*j)*KPITCH + d2];
                S[j] += a0.x*kk.x; S[j] += a0.y*kk.y;
            }
        }
        float p[6]; float inv;
        {
            float mx = S[0] * SCALE;
#pragma unroll
            for (int j = 1; j < 6; j++) mx = fmaxf(mx, S[j]*SCALE);
#pragma unroll
            for (int o = 8; o > 0; o >>= 1) mx = fmaxf(mx, __shfl_xor_sync(0xffffffffu, mx, o));
            float sum = 0.f;
#pragma unroll
            for (int j = 0; j < 6; j++) { p[j] = __expf(S[j]*SCALE - mx); sum += p[j]; }
#pragma unroll
            for (int o = 8; o > 0; o >>= 1) sum += __shfl_xor_sync(0xffffffffu, sum, o);
            inv = 1.f / sum;
        }
        __syncthreads();
#pragma unroll
        for (int j = 0; j < 6; j++)
            Ss[ty*SPITCH + tx + 16*j] = p[j] * inv;
#pragma unroll
        for (int i = 0; i < 6; i++) {
            int lin = tid + i*NT;
            int row = lin >> 5, c4 = lin & 31;
            int node = mem[row];
            float4 v = *(const float4*)&g_p[2*PSZ + node*HD + head*DD + c4*4];
            float mu = s_mu[128+row], rs = s_rs[128+row];
            KV[(c4*4+0)*VPITCH + row] = fmaxf((v.x-mu)*rs*s_g[256+c4*4+0] + s_b[256+c4*4+0], 0.f);
            KV[(c4*4+1)*VPITCH + row] = fmaxf((v.y-mu)*rs*s_g[256+c4*4+1] + s_b[256+c4*4+1], 0.f);
            KV[(c4*4+2)*VPITCH + row] = fmaxf((v.z-mu)*rs*s_g[256+c4*4+2] + s_b[256+c4*4+2], 0.f);
            KV[(c4*4+3)*VPITCH + row] = fmaxf((v.w-mu)*rs*s_g[256+c4*4+3] + s_b[256+c4*4+3], 0.f);
        }
        __syncthreads();
        float acc[8] = {};
#pragma unroll 4
        for (int k2 = 0; k2 < MM; k2 += 2) {
            float2 s0 = *(float2*)&Ss[ty*SPITCH + k2];
#pragma unroll
            for (int j = 0; j < 8; j++) {
                float2 vv = *(float2*)&KV[(tx + 16*j)*VPITCH + k2];
                acc[j] += s0.x*vv.x; acc[j] += s0.y*vv.y;
            }
        }
        {
            int node = mem[rb*32 + ty];
#pragma unroll
            for (int j = 0; j < 8; j++)
                g_att[node*HD + head*DD + tx + 16*j] = acc[j];
        }
    }
    gsync(base, 2);

    // ===== stage 3: o1 split-K via 3xtf32 mma (24 mt x 6 splits) =========
    {
        uint32_t* Ah = (uint32_t*)sm;          // 32 x 68
        uint32_t* Al = Ah + 32*68;
        uint32_t* Wh = Al + 32*68;             // 128 x 68
        uint32_t* Wl = Wh + 128*68;
        int sp = bid / 24, mt = bid % 24;
        int m0 = mt*32, kb = sp*128;
        int w = tid >> 5, l = tid & 31;
        int g = l >> 2, t4 = l & 3;
        float acc[2][4] = {};
        for (int kc = 0; kc < 2; kc++) {
            int k0 = kb + kc*64;
            __syncthreads();   // prior mma frag reads complete
            {
                int row = tid >> 4, c4 = tid & 15;
                float4 v = *(const float4*)&g_att[(m0+row)*HD + k0 + c4*4];
                int bse = row*68 + c4*4;
                float xs[4] = {v.x, v.y, v.z, v.w};
#pragma unroll
                for (int c = 0; c < 4; c++) {
                    uint32_t hb = f2tf(xs[c]);
                    Ah[bse+c] = hb;
                    Al[bse+c] = f2tf(xs[c] - __uint_as_float(hb));
                }
            }
#pragma unroll
            for (int i = 0; i < 4; i++) {
                int lin = tid + i*NT;
                int row = lin >> 4, c4 = lin & 15;
                float4 v = *(const float4*)&Wo1[row*HD + k0 + c4*4];
                int bse = row*68 + c4*4;
                float xs[4] = {v.x, v.y, v.z, v.w};
#pragma unroll
                for (int c = 0; c < 4; c++) {
                    uint32_t hb = f2tf(xs[c]);
                    Wh[bse+c] = hb;
                    Wl[bse+c] = f2tf(xs[c] - __uint_as_float(hb));
                }
            }
            __syncthreads();
#pragma unroll
            for (int ks = 0; ks < 8; ks++) {
                int kk = ks*8 + t4;
                int br = (w*8 + g)*68 + kk;
                uint32_t bh[2] = {Wh[br], Wh[br+4]};
                uint32_t bl[2] = {Wl[br], Wl[br+4]};
#pragma unroll
                for (int tt = 0; tt < 2; tt++) {
                    int ar = (tt*16 + g)*68 + kk;
                    uint32_t ah[4] = {Ah[ar], Ah[ar+8*68], Ah[ar+4], Ah[ar+8*68+4]};
                    uint32_t al[4] = {Al[ar], Al[ar+8*68], Al[ar+4], Al[ar+8*68+4]};
                    mma_tf32(acc[tt], ah, bh);
                    mma_tf32(acc[tt], ah, bl);
                    mma_tf32(acc[tt], al, bh);
                }
            }
        }
#pragma unroll
        for (int tt = 0; tt < 2; tt++) {
            int r0 = tt*16 + g;
            int col = w*8 + 2*t4;
            *(float2*)&g_part[sp*(NN*DD) + (m0+r0)*DD + col]   = make_float2(acc[tt][0], acc[tt][1]);
            *(float2*)&g_part[sp*(NN*DD) + (m0+r0+8)*DD + col] = make_float2(acc[tt][2], acc[tt][3]);
        }
    }
    gsync(base, 3);

    // ====== stage 4: reduce+LN -> mid GEMM+LN -> final GEMM+res+scatter ==
    if (bid < 96) {
        float* nodes_s = sm;                 // 8 x 130
        float* r1_s    = sm + 8*130;         // 8 x 130
        float* h_s     = sm + 2*8*130;       // 8 x 130
        float* Bs      = sm + 3*8*130;       // 128 x 34
        float* red     = sm + 3*8*130 + 128*34;  // 16 x 2
        int m0 = bid*8;
        int row  = tid >> 6;        // 0..7 (row spans 2 warps)
        int lane = tid & 63;
        int wid  = tid >> 5;
        const float* Ab = m0 < NA ? agents + m0*DD : lanes + (m0 - NA)*DD;
        if (tid < 256) {
            int rw = tid >> 5, c4 = tid & 31;
            float4 v = *(const float4*)&Ab[rw*DD + c4*4];
            float* d = &nodes_s[rw*130 + c4*4];
            d[0]=v.x; d[1]=v.y; d[2]=v.z; d[3]=v.w;
            float4 sv = make_float4(0.f,0.f,0.f,0.f);
#pragma unroll
            for (int sp = 0; sp < 6; sp++) {
                float4 u = *(const float4*)&g_part[sp*(NN*DD) + (m0+rw)*DD + c4*4];
                sv.x += u.x; sv.y += u.y; sv.z += u.z; sv.w += u.w;
            }
            float* e = &r1_s[rw*130 + c4*4];
            e[0]=sv.x; e[1]=sv.y; e[2]=sv.z; e[3]=sv.w;
        }
        __syncthreads();
        {
            float x0 = r1_s[row*130 + lane];
            float x1 = r1_s[row*130 + lane + 64];
            float s = x0 + x1, s2 = x0*x0 + x1*x1;
#pragma unroll
            for (int o = 16; o > 0; o >>= 1) {
                s  += __shfl_xor_sync(0xffffffffu, s,  o);
                s2 += __shfl_xor_sync(0xffffffffu, s2, o);
            }
            if ((tid & 31) == 0) { red[wid*2] = s; red[wid*2+1] = s2; }
            __syncthreads();
            float ss  = red[(wid^1)*2]   + red[wid*2];
            float ss2 = red[(wid^1)*2+1] + red[wid*2+1];
            float mu = ss*(1.f/DD), var = ss2*(1.f/DD) - mu*mu;
            float rstd = rsqrtf(var + 1e-5f);
            r1_s[row*130 + lane]      = fmaxf((x0-mu)*rstd*go1[lane]    + bo1[lane],    0.f);
            r1_s[row*130 + lane + 64] = fmaxf((x1-mu)*rstd*go1[lane+64] + bo1[lane+64], 0.f);
        }
        __syncthreads();
        float acc[2] = {};
        for (int cc = 0; cc < 8; cc++) {
            const float* W = cc < 4 ? W1 : Wo2;
            const float* A = cc < 4 ? nodes_s : r1_s;
            int k0 = (cc & 3) * 32;
#pragma unroll
            for (int i = 0; i < 2; i++) {
                int lin = tid + i*NT;
                int rw = lin >> 3, c4 = lin & 7;
                float4 v = *(const float4*)&W[rw*DD + k0 + c4*4];
                float* d = &Bs[rw*34 + c4*4];
                d[0]=v.x; d[1]=v.y; d[2]=v.z; d[3]=v.w;
            }
            __syncthreads();
#pragma unroll 4
            for (int k2 = 0; k2 < 32; k2 += 2) {
                float2 a = *(float2*)&A[row*130 + k0 + k2];
#pragma unroll
                for (int j = 0; j < 2; j++) {
                    float2 b = *(float2*)&Bs[(lane + 64*j)*34 + k2];
                    acc[j] += a.x*b.x; acc[j] += a.y*b.y;
                }
            }
            __syncthreads();
        }
        {
            float s = acc[0] + acc[1], s2 = acc[0]*acc[0] + acc[1]*acc[1];
#pragma unroll
            for (int o = 16; o > 0; o >>= 1) {
                s  += __shfl_xor_sync(0xffffffffu, s,  o);
                s2 += __shfl_xor_sync(0xffffffffu, s2, o);
            }
            if ((tid & 31) == 0) { red[wid*2] = s; red[wid*2+1] = s2; }
            __syncthreads();
            float ss  = red[(wid^1)*2]   + red[wid*2];
            float ss2 = red[(wid^1)*2+1] + red[wid*2+1];
            float mu = ss*(1.f/DD), var = ss2*(1.f/DD) - mu*mu;
            float rstd = rsqrtf(var + 1e-5f);
            h_s[row*130 + lane]      = fmaxf((acc[0]-mu)*rstd*gn[lane]    + bn[lane],    0.f);
            h_s[row*130 + lane + 64] = fmaxf((acc[1]-mu)*rstd*gn[lane+64] + bn[lane+64], 0.f);
        }
        __syncthreads();
        float acc2[2] = {};
        for (int cc = 0; cc < 4; cc++) {
            int k0 = cc * 32;
#pragma unroll
            for (int i = 0; i < 2; i++) {
                int lin = tid + i*NT;
                int rw = lin >> 3, c4 = lin & 7;
                float4 v = *(const float4*)&W2[rw*DD + k0 + c4*4];
                float* d = &Bs[rw*34 + c4*4];
                d[0]=v.x; d[1]=v.y; d[2]=v.z; d[3]=v.w;
            }
            __syncthreads();
#pragma unroll 4
            for (int k2 = 0; k2 < 32; k2 += 2) {
                float2 a = *(float2*)&h_s[row*130 + k0 + k2];
#pragma unroll
                for (int j = 0; j < 2; j++) {
                    float2 b = *(float2*)&Bs[(lane + 64*j)*34 + k2];
                    acc2[j] += a.x*b.x; acc2[j] += a.y*b.y;
                }
            }
            __syncthreads();
        }
        int orow = g_inv[m0 + row];
#pragma unroll
        for (int j = 0; j < 2; j++) {
            int c = lane + 64*j;
            out[orow*DD + c] = fmaxf(acc2[j] + nodes_s[row*130 + c], 0.f);
        }
    }
}

// ------------------------------------------------------------------------
extern "C" void kernel_launch(void* const* d_in, const int* in_sizes, int n_in,
                              void* d_out, int out_size) {
    const float* agents    = (const float*)d_in[0];
    const int*   agent_ids = (const int*)  d_in[1];
    const float* lanes     = (const float*)d_in[2];
    const int*   lane_ids  = (const int*)  d_in[3];
    const float* Wq  = (const float*)d_in[4];
    const float* gq  = (const float*)d_in[5];
    const float* bq  = (const float*)d_in[6];
    const float* Wk  = (const float*)d_in[7];
    const float* gk  = (const float*)d_in[8];
    const float* bk  = (const float*)d_in[9];
    const float* Wv  = (const float*)d_in[10];
    const float* gv  = (const float*)d_in[11];
    const float* bv  = (const float*)d_in[12];
    const float* Wo1 = (const float*)d_in[13];
    const float* go1 = (const float*)d_in[14];
    const float* bo1 = (const float*)d_in[15];
    const float* Wo2 = (const float*)d_in[16];
    const float* W1  = (const float*)d_in[17];
    const float* gn  = (const float*)d_in[18];
    const float* bn  = (const float*)d_in[19];
    const float* W2  = (const float*)d_in[20];
    float* out = (float*)d_out;

    cudaFuncSetAttribute(megak, cudaFuncAttributeMaxDynamicSharedMemorySize, DYN_SMEM);

    megak<<<NB, NT, DYN_SMEM>>>(agents, agent_ids, lanes, lane_ids,
                                Wq, gq, bq, Wk, gk, bk, Wv, gv, bv,
                                Wo1, go1, bo1, Wo2, W1, gn, bn, W2, out);
}

// round 11
// speedup vs baseline: 1.2599x; 1.0967x over previous
#include <cuda_runtime.h>
#include <cstdint>

#define NN 768
#define NA 192
#define DD 128
#define HH 6
#define HD 768
#define MM 96
#define PSZ (HD*NN)
#define SCALE 0.08838834764831845f
#define NB 144
#define NT 512

// ---------------- device scratch ----------------
__device__ float g_p[3*PSZ];          // raw q,k,v projections (pre-LN)
__device__ float g_psum[3*NN*24];     // per (mat,row): 12 chunks x (sum, sumsq)
__device__ float g_att[NN*HD];        // attention output
__device__ float g_part[6*NN*DD];     // o1 split-K partials
__device__ int   g_inv[NN];           // node -> output row
__device__ unsigned int g_count = 0;
__device__ unsigned int g_gen = 0;

__device__ __forceinline__ void gsync(unsigned int base, unsigned int i) {
    __threadfence();
    __syncthreads();
    if (threadIdx.x == 0) {
        unsigned int old = atomicInc(&g_count, NB - 1u);
        if (old == NB - 1u) {
            atomicExch(&g_gen, base + i);
        } else {
            while ((*(volatile unsigned int*)&g_gen - base) < i) { }
            __threadfence();
        }
    }
    __syncthreads();
}

// tf32 helpers
__device__ __forceinline__ uint32_t f2tf(float x) {
    uint32_t r;
    asm("cvt.rna.tf32.f32 %0, %1;" : "=r"(r) : "f"(x));
    return r;
}
__device__ __forceinline__ void mma_tf32(float* d, const uint32_t* a, const uint32_t* b) {
    asm("mma.sync.aligned.m16n8k8.row.col.f32.tf32.tf32.f32 "
        "{%0,%1,%2,%3}, {%4,%5,%6,%7}, {%8,%9}, {%0,%1,%2,%3};"
        : "+f"(d[0]), "+f"(d[1]), "+f"(d[2]), "+f"(d[3])
        : "r"(a[0]), "r"(a[1]), "r"(a[2]), "r"(a[3]), "r"(b[0]), "r"(b[1]));
}

// max smem across stages: stage2 = 35104 floats = 140416 B
#define DYN_SMEM (35104*4)

__global__ void __launch_bounds__(NT) megak(
    const float* __restrict__ agents, const int* __restrict__ agent_ids,
    const float* __restrict__ lanes,  const int* __restrict__ lane_ids,
    const float* __restrict__ Wq, const float* __restrict__ gq, const float* __restrict__ bq,
    const float* __restrict__ Wk, const float* __restrict__ gk, const float* __restrict__ bk,
    const float* __restrict__ Wv, const float* __restrict__ gv, const float* __restrict__ bv,
    const float* __restrict__ Wo1, const float* __restrict__ go1, const float* __restrict__ bo1,
    const float* __restrict__ Wo2, const float* __restrict__ W1,
    const float* __restrict__ gn, const float* __restrict__ bn,
    const float* __restrict__ W2, float* __restrict__ out)
{
    extern __shared__ float sm[];
    int tid = threadIdx.x;
    int bid = blockIdx.x;
    unsigned int base = 0;
    if (tid == 0) base = *(volatile unsigned int*)&g_gen;

    if (bid == 0) {
        for (int t = tid; t < NN; t += NT) {
            if (t < NA) g_inv[agent_ids[t]] = t;
            else        g_inv[NA + lane_ids[t - NA]] = t;
        }
    }

    // ===== stage 1: QKV GEMM via 3xtf32 mma (144 jobs: 12 mt x 12 nch) ===
    {
        uint32_t* As_hi = (uint32_t*)sm;
        uint32_t* As_lo = As_hi + 64*132;
        uint32_t* Ws_hi = As_lo + 64*132;
        uint32_t* Ws_lo = Ws_hi + 64*132;
        float*    Cs    = (float*)Ws_hi;      // alias, pitch 68, 64x68
        int mt = bid % 12, nch = bid / 12;
        int m0 = mt*64, w0 = nch*64;
        const float* Ab = m0 < NA ? agents + m0*DD : lanes + (m0 - NA)*DD;
#pragma unroll
        for (int i = 0; i < 4; i++) {
            int lin = tid + i*NT;
            int row = lin >> 5, c4 = lin & 31;
            float4 v = *(const float4*)&Ab[row*DD + c4*4];
            int bse = row*132 + c4*4;
            float xs[4] = {v.x, v.y, v.z, v.w};
#pragma unroll
            for (int c = 0; c < 4; c++) {
                uint32_t hb = f2tf(xs[c]);
                As_hi[bse+c] = hb;
                As_lo[bse+c] = f2tf(xs[c] - __uint_as_float(hb));
            }
        }
        int w = tid >> 5, l = tid & 31;
        int nb = w & 7, mgrp = w >> 3;
        int g = l >> 2, t4 = l & 3;
        for (int sel = 0; sel < 3; sel++) {
            const float* W = sel == 0 ? Wq : (sel == 1 ? Wk : Wv);
            __syncthreads();
#pragma unroll
            for (int i = 0; i < 4; i++) {
                int lin = tid + i*NT;
                int row = lin >> 5, c4 = lin & 31;
                float4 v = *(const float4*)&W[(w0+row)*DD + c4*4];
                int bse = row*132 + c4*4;
                float xs[4] = {v.x, v.y, v.z, v.w};
#pragma unroll
                for (int c = 0; c < 4; c++) {
                    uint32_t hb = f2tf(xs[c]);
                    Ws_hi[bse+c] = hb;
                    Ws_lo[bse+c] = f2tf(xs[c] - __uint_as_float(hb));
                }
            }
            __syncthreads();
            float acc[2][4] = {};
#pragma unroll
            for (int ks = 0; ks < 16; ks++) {
                int k0 = ks*8 + t4;
                int br = (nb*8 + g)*132 + k0;
                uint32_t bh[2] = {Ws_hi[br], Ws_hi[br+4]};
                uint32_t bl[2] = {Ws_lo[br], Ws_lo[br+4]};
#pragma unroll
                for (int tt = 0; tt < 2; tt++) {
                    int ar = ((mgrp*2+tt)*16 + g)*132 + k0;
                    uint32_t ah[4] = {As_hi[ar], As_hi[ar+8*132], As_hi[ar+4], As_hi[ar+8*132+4]};
                    uint32_t al[4] = {As_lo[ar], As_lo[ar+8*132], As_lo[ar+4], As_lo[ar+8*132+4]};
                    mma_tf32(acc[tt], ah, bh);
                    mma_tf32(acc[tt], ah, bl);
                    mma_tf32(acc[tt], al, bh);
                }
            }
            __syncthreads();
#pragma unroll
            for (int tt = 0; tt < 2; tt++) {
                int r0 = (mgrp*2+tt)*16 + g;
                int col = nb*8 + 2*t4;
                *(float2*)&Cs[r0*68 + col]     = make_float2(acc[tt][0], acc[tt][1]);
                *(float2*)&Cs[(r0+8)*68 + col] = make_float2(acc[tt][2], acc[tt][3]);
            }
            __syncthreads();
            {
                int row = tid >> 3, q = tid & 7;
                float4 v0 = *(float4*)&Cs[row*68 + q*8];
                float4 v1 = *(float4*)&Cs[row*68 + q*8 + 4];
                float s  = v0.x+v0.y+v0.z+v0.w + v1.x+v1.y+v1.z+v1.w;
                float s2 = v0.x*v0.x+v0.y*v0.y+v0.z*v0.z+v0.w*v0.w
                         + v1.x*v1.x+v1.y*v1.y+v1.z*v1.z+v1.w*v1.w;
#pragma unroll
                for (int o = 4; o > 0; o >>= 1) {
                    s  += __shfl_xor_sync(0xffffffffu, s,  o);
                    s2 += __shfl_xor_sync(0xffffffffu, s2, o);
                }
                float* gp = &g_p[sel*PSZ + (m0+row)*HD + w0 + q*8];
                *(float4*)gp = v0;
                *(float4*)(gp+4) = v1;
                if (q == 0) {
                    g_psum[(sel*NN + m0+row)*24 + nch*2 + 0] = s;
                    g_psum[(sel*NN + m0+row)*24 + nch*2 + 1] = s2;
                }
            }
        }
    }
    gsync(base, 1);

    // ===== stage 2: tensor-core attention (144 jobs, 1/block) ============
    {
        uint32_t* Qhi = (uint32_t*)sm;          // 32 x 132
        uint32_t* Qlo = Qhi + 4224;
        uint32_t* Khi = Qhi + 8448;             // 96 x 132
        uint32_t* Klo = Qhi + 21120;
        // phase-2 aliases (Q/K dead by then)
        float*    Sraw = sm;                    // 32 x 100 raw scores
        uint32_t* Shi  = (uint32_t*)sm;         // 32 x 100
        uint32_t* Slo  = Shi + 3200;
        uint32_t* Vthi = Shi + 6400;            // 128 x 100 (n-major: [dim][s])
        uint32_t* Vtlo = Shi + 19200;
        float* s_mu = sm + 33792;
        float* s_rs = sm + 34016;
        float* s_g  = sm + 34240;
        float* s_b  = sm + 34624;
        int*   mem  = (int*)(sm + 35008);

        int rb = bid % 3, head = (bid/3) % HH, gph = bid / (3*HH);
        if (tid < MM)
            mem[tid] = tid < 24 ? agent_ids[gph*24 + tid]
                                : NA + lane_ids[gph*72 + (tid - 24)];
        __syncthreads();
        if (tid < 224) {
            int mat, node;
            if (tid < 32)       { mat = 0; node = mem[rb*32 + tid]; }
            else if (tid < 128) { mat = 1; node = mem[tid - 32]; }
            else                { mat = 2; node = mem[tid - 128]; }
            const float* ps = &g_psum[(mat*NN + node)*24];
            float s = 0.f, s2 = 0.f;
#pragma unroll
            for (int n = 0; n < 12; n++) { s += ps[2*n]; s2 += ps[2*n+1]; }
            float mu = s * (1.f/HD);
            float var = s2 * (1.f/HD) - mu*mu;
            s_mu[tid] = mu;
            s_rs[tid] = rsqrtf(var + 1e-5f);
        }
        for (int t = tid; t < 384; t += NT) {
            int mat = t >> 7, c = t & 127;
            const float* g  = mat==0 ? gq : (mat==1 ? gk : gv);
            const float* bb = mat==0 ? bq : (mat==1 ? bk : bv);
            s_g[t] = g[head*DD + c];
            s_b[t] = bb[head*DD + c];
        }
        __syncthreads();
        // Q (32 rows) LN + hi/lo split, pitch 132
#pragma unroll
        for (int i = 0; i < 2; i++) {
            int lin = tid + i*NT;
            int row = lin >> 5, c4 = lin & 31;
            int node = mem[rb*32 + row];
            float4 v = *(const float4*)&g_p[node*HD + head*DD + c4*4];
            float mu = s_mu[row], rs = s_rs[row];
            float xs[4];
            xs[0] = (v.x-mu)*rs*s_g[c4*4+0] + s_b[c4*4+0];
            xs[1] = (v.y-mu)*rs*s_g[c4*4+1] + s_b[c4*4+1];
            xs[2] = (v.z-mu)*rs*s_g[c4*4+2] + s_b[c4*4+2];
            xs[3] = (v.w-mu)*rs*s_g[c4*4+3] + s_b[c4*4+3];
            uint4 h, lo2;
            h.x = f2tf(xs[0]); lo2.x = f2tf(xs[0] - __uint_as_float(h.x));
            h.y = f2tf(xs[1]); lo2.y = f2tf(xs[1] - __uint_as_float(h.y));
            h.z = f2tf(xs[2]); lo2.z = f2tf(xs[2] - __uint_as_float(h.z));
            h.w = f2tf(xs[3]); lo2.w = f2tf(xs[3] - __uint_as_float(h.w));
            *(uint4*)&Qhi[row*132 + c4*4] = h;
            *(uint4*)&Qlo[row*132 + c4*4] = lo2;
        }
        // K (96 rows) LN + split, pitch 132
#pragma unroll
        for (int i = 0; i < 6; i++) {
            int lin = tid + i*NT;
            int row = lin >> 5, c4 = lin & 31;
            int node = mem[row];
            float4 v = *(const float4*)&g_p[PSZ + node*HD + head*DD + c4*4];
            float mu = s_mu[32+row], rs = s_rs[32+row];
            float xs[4];
            xs[0] = (v.x-mu)*rs*s_g[128+c4*4+0] + s_b[128+c4*4+0];
            xs[1] = (v.y-mu)*rs*s_g[128+c4*4+1] + s_b[128+c4*4+1];
            xs[2] = (v.z-mu)*rs*s_g[128+c4*4+2] + s_b[128+c4*4+2];
            xs[3] = (v.w-mu)*rs*s_g[128+c4*4+3] + s_b[128+c4*4+3];
            uint4 h, lo2;
            h.x = f2tf(xs[0]); lo2.x = f2tf(xs[0] - __uint_as_float(h.x));
            h.y = f2tf(xs[1]); lo2.y = f2tf(xs[1] - __uint_as_float(h.y));
            h.z = f2tf(xs[2]); lo2.z = f2tf(xs[2] - __uint_as_float(h.z));
            h.w = f2tf(xs[3]); lo2.w = f2tf(xs[3] - __uint_as_float(h.w));
            *(uint4*)&Khi[row*132 + c4*4] = h;
            *(uint4*)&Klo[row*132 + c4*4] = lo2;
        }
        __syncthreads();

        int w = tid >> 5, l = tid & 31;
        int g = l >> 2, t4 = l & 3;
        // scores: S[32,96] = Q @ K^T, warps 0..11 (n-tile = w), both m-tiles
        float accS[2][4] = {};
        if (w < 12) {
#pragma unroll
            for (int ks = 0; ks < 16; ks++) {
                int k0 = ks*8 + t4;
                int br = (w*8 + g)*132 + k0;
                uint32_t bh[2] = {Khi[br], Khi[br+4]};
                uint32_t bl[2] = {Klo[br], Klo[br+4]};
#pragma unroll
                for (int mt = 0; mt < 2; mt++) {
                    int ar = (mt*16 + g)*132 + k0;
                    uint32_t ah[4] = {Qhi[ar], Qhi[ar+1056], Qhi[ar+4], Qhi[ar+1060]};
                    uint32_t al[4] = {Qlo[ar], Qlo[ar+1056], Qlo[ar+4], Qlo[ar+1060]};
                    mma_tf32(accS[mt], ah, bh);
                    mma_tf32(accS[mt], ah, bl);
                    mma_tf32(accS[mt], al, bh);
                }
            }
        }
        __syncthreads();   // Q/K reads complete; alias region reusable
        if (w < 12) {
#pragma unroll
            for (int mt = 0; mt < 2; mt++) {
                int r0 = mt*16 + g;
                int col = w*8 + 2*t4;
                *(float2*)&Sraw[r0*100 + col]     = make_float2(accS[mt][0]*SCALE, accS[mt][1]*SCALE);
                *(float2*)&Sraw[(r0+8)*100 + col] = make_float2(accS[mt][2]*SCALE, accS[mt][3]*SCALE);
            }
        }
        __syncthreads();
        // softmax: warp w handles rows 2w, 2w+1; lane covers cols l, l+32, l+64
#pragma unroll
        for (int i = 0; i < 2; i++) {
            int r = 2*w + i;
            float x0 = Sraw[r*100 + l];
            float x1 = Sraw[r*100 + l + 32];
            float x2 = Sraw[r*100 + l + 64];
            float mx = fmaxf(x0, fmaxf(x1, x2));
#pragma unroll
            for (int o = 16; o > 0; o >>= 1) mx = fmaxf(mx, __shfl_xor_sync(0xffffffffu, mx, o));
            float p0 = __expf(x0 - mx), p1 = __expf(x1 - mx), p2 = __expf(x2 - mx);
            float sum = p0 + p1 + p2;
#pragma unroll
            for (int o = 16; o > 0; o >>= 1) sum += __shfl_xor_sync(0xffffffffu, sum, o);
            float inv = 1.f / sum;
            p0 *= inv; p1 *= inv; p2 *= inv;
            uint32_t h0 = f2tf(p0), h1 = f2tf(p1), h2 = f2tf(p2);
            Shi[r*100 + l]      = h0; Slo[r*100 + l]      = f2tf(p0 - __uint_as_float(h0));
            Shi[r*100 + l + 32] = h1; Slo[r*100 + l + 32] = f2tf(p1 - __uint_as_float(h1));
            Shi[r*100 + l + 64] = h2; Slo[r*100 + l + 64] = f2tf(p2 - __uint_as_float(h2));
        }
        // V^T fill (disjoint region, same phase): task t -> (dim, rowgroup)
#pragma unroll 4
        for (int i = 0; i < 24; i++) {
            int t = w + i*16;
            int dim = t / 3, rg = t - 3*dim;
            int row = rg*32 + l;
            int node = mem[row];
            float x = g_p[2*PSZ + node*HD + head*DD + dim];
            x = (x - s_mu[128+row]) * s_rs[128+row] * s_g[256+dim] + s_b[256+dim];
            x = fmaxf(x, 0.f);
            uint32_t h = f2tf(x);
            Vthi[dim*100 + row] = h;
            Vtlo[dim*100 + row] = f2tf(x - __uint_as_float(h));
        }
        __syncthreads();
        // out = S @ V : M=32, N=128 (n-tile = w), K=96
        float accO[2][4] = {};
#pragma unroll
        for (int ks = 0; ks < 12; ks++) {
            int k0 = ks*8 + t4;
            int br = (w*8 + g)*100 + k0;
            uint32_t bh[2] = {Vthi[br], Vthi[br+4]};
            uint32_t bl[2] = {Vtlo[br], Vtlo[br+4]};
#pragma unroll
            for (int mt = 0; mt < 2; mt++) {
                int ar = (mt*16 + g)*100 + k0;
                uint32_t ah[4] = {Shi[ar], Shi[ar+800], Shi[ar+4], Shi[ar+804]};
                uint32_t al[4] = {Slo[ar], Slo[ar+800], Slo[ar+4], Slo[ar+804]};
                mma_tf32(accO[mt], ah, bh);
                mma_tf32(accO[mt], al, bh);
                mma_tf32(accO[mt], ah, bl);
            }
        }
#pragma unroll
        for (int mt = 0; mt < 2; mt++) {
            int r0 = mt*16 + g;
            int n0 = w*8 + 2*t4;
            int node0 = mem[rb*32 + r0];
            *(float2*)&g_att[node0*HD + head*DD + n0] = make_float2(accO[mt][0], accO[mt][1]);
            int node1 = mem[rb*32 + r0 + 8];
            *(float2*)&g_att[node1*HD + head*DD + n0] = make_float2(accO[mt][2], accO[mt][3]);
        }
    }
    gsync(base, 2);

    // ===== stage 3: o1 split-K via 3xtf32 mma (24 mt x 6 splits) =========
    {
        uint32_t* Ah = (uint32_t*)sm;          // 32 x 68
        uint32_t* Al = Ah + 32*68;
        uint32_t* Wh = Al + 32*68;             // 128 x 68
        uint32_t* Wl = Wh + 128*68;
        int sp = bid / 24, mt = bid % 24;
        int m0 = mt*32, kb = sp*128;
        int w = tid >> 5, l = tid & 31;
        int g = l >> 2, t4 = l & 3;
        float acc[2][4] = {};
        for (int kc = 0; kc < 2; kc++) {
            int k0 = kb + kc*64;
            __syncthreads();
            {
                int row = tid >> 4, c4 = tid & 15;
                float4 v = *(const float4*)&g_att[(m0+row)*HD + k0 + c4*4];
                int bse = row*68 + c4*4;
                float xs[4] = {v.x, v.y, v.z, v.w};
#pragma unroll
                for (int c = 0; c < 4; c++) {
                    uint32_t hb = f2tf(xs[c]);
                    Ah[bse+c] = hb;
                    Al[bse+c] = f2tf(xs[c] - __uint_as_float(hb));
                }
            }
#pragma unroll
            for (int i = 0; i < 4; i++) {
                int lin = tid + i*NT;
                int row = lin >> 4, c4 = lin & 15;
                float4 v = *(const float4*)&Wo1[row*HD + k0 + c4*4];
                int bse = row*68 + c4*4;
                float xs[4] = {v.x, v.y, v.z, v.w};
#pragma unroll
                for (int c = 0; c < 4; c++) {
                    uint32_t hb = f2tf(xs[c]);
                    Wh[bse+c] = hb;
                    Wl[bse+c] = f2tf(xs[c] - __uint_as_float(hb));
                }
            }
            __syncthreads();
#pragma unroll
            for (int ks = 0; ks < 8; ks++) {
                int kk = ks*8 + t4;
                int br = (w*8 + g)*68 + kk;
                uint32_t bh[2] = {Wh[br], Wh[br+4]};
                uint32_t bl[2] = {Wl[br], Wl[br+4]};
#pragma unroll
                for (int tt = 0; tt < 2; tt++) {
                    int ar = (tt*16 + g)*68 + kk;
                    uint32_t ah[4] = {Ah[ar], Ah[ar+8*68], Ah[ar+4], Ah[ar+8*68+4]};
                    uint32_t al[4] = {Al[ar], Al[ar+8*68], Al[ar+4], Al[ar+8*68+4]};
                    mma_tf32(acc[tt], ah, bh);
                    mma_tf32(acc[tt], ah, bl);
                    mma_tf32(acc[tt], al, bh);
                }
            }
        }
#pragma unroll
        for (int tt = 0; tt < 2; tt++) {
            int r0 = tt*16 + g;
            int col = w*8 + 2*t4;
            *(float2*)&g_part[sp*(NN*DD) + (m0+r0)*DD + col]   = make_float2(acc[tt][0], acc[tt][1]);
            *(float2*)&g_part[sp*(NN*DD) + (m0+r0+8)*DD + col] = make_float2(acc[tt][2], acc[tt][3]);
        }
    }
    gsync(base, 3);

    // ====== stage 4: reduce+LN -> mid GEMM+LN -> final GEMM+res+scatter ==
    if (bid < 96) {
        float* nodes_s = sm;                 // 8 x 130
        float* r1_s    = sm + 8*130;         // 8 x 130
        float* h_s     = sm + 2*8*130;       // 8 x 130
        float* Bs      = sm + 3*8*130;       // 128 x 34
        float* red     = sm + 3*8*130 + 128*34;  // 16 x 2
        int m0 = bid*8;
        int row  = tid >> 6;        // 0..7 (row spans 2 warps)
        int lane = tid & 63;
        int wid  = tid >> 5;
        const float* Ab = m0 < NA ? agents + m0*DD : lanes + (m0 - NA)*DD;
        if (tid < 256) {
            int rw = tid >> 5, c4 = tid & 31;
            float4 v = *(const float4*)&Ab[rw*DD + c4*4];
            float* d = &nodes_s[rw*130 + c4*4];
            d[0]=v.x; d[1]=v.y; d[2]=v.z; d[3]=v.w;
            float4 sv = make_float4(0.f,0.f,0.f,0.f);
#pragma unroll
            for (int sp = 0; sp < 6; sp++) {
                float4 u = *(const float4*)&g_part[sp*(NN*DD) + (m0+rw)*DD + c4*4];
                sv.x += u.x; sv.y += u.y; sv.z += u.z; sv.w += u.w;
            }
            float* e = &r1_s[rw*130 + c4*4];
            e[0]=sv.x; e[1]=sv.y; e[2]=sv.z; e[3]=sv.w;
        }
        __syncthreads();
        {
            float x0 = r1_s[row*130 + lane];
            float x1 = r1_s[row*130 + lane + 64];
            float s = x0 + x1, s2 = x0*x0 + x1*x1;
#pragma unroll
            for (int o = 16; o > 0; o >>= 1) {
                s  += __shfl_xor_sync(0xffffffffu, s,  o);
                s2 += __shfl_xor_sync(0xffffffffu, s2, o);
            }
            if ((tid & 31) == 0) { red[wid*2] = s; red[wid*2+1] = s2; }
            __syncthreads();
            float ss  = red[(wid^1)*2]   + red[wid*2];
            float ss2 = red[(wid^1)*2+1] + red[wid*2+1];
            float mu = ss*(1.f/DD), var = ss2*(1.f/DD) - mu*mu;
            float rstd = rsqrtf(var + 1e-5f);
            r1_s[row*130 + lane]      = fmaxf((x0-mu)*rstd*go1[lane]    + bo1[lane],    0.f);
            r1_s[row*130 + lane + 64] = fmaxf((x1-mu)*rstd*go1[lane+64] + bo1[lane+64], 0.f);
        }
        __syncthreads();
        // mid GEMM with register prefetch of W chunks
        float acc[2] = {};
        float4 wreg[2];
        {
            int lin0 = tid, lin1 = tid + NT;
            wreg[0] = *(const float4*)&W1[(lin0>>3)*DD + (lin0&7)*4];
            wreg[1] = *(const float4*)&W1[(lin1>>3)*DD + (lin1&7)*4];
        }
        for (int cc = 0; cc < 8; cc++) {
#pragma unroll
            for (int i = 0; i < 2; i++) {
                int lin = tid + i*NT;
                int rw = lin >> 3, c4 = lin & 7;
                float* d = &Bs[rw*34 + c4*4];
                d[0]=wreg[i].x; d[1]=wreg[i].y; d[2]=wreg[i].z; d[3]=wreg[i].w;
            }
            if (cc < 7) {
                const float* Wn = (cc+1) < 4 ? W1 : Wo2;
                int k0n = ((cc+1) & 3) * 32;
#pragma unroll
                for (int i = 0; i < 2; i++) {
                    int lin = tid + i*NT;
                    wreg[i] = *(const float4*)&Wn[(lin>>3)*DD + k0n + (lin&7)*4];
                }
            }
            const float* A = cc < 4 ? nodes_s : r1_s;
            int k0 = (cc & 3) * 32;
            __syncthreads();
#pragma unroll 4
            for (int k2 = 0; k2 < 32; k2 += 2) {
                float2 a = *(float2*)&A[row*130 + k0 + k2];
#pragma unroll
                for (int j = 0; j < 2; j++) {
                    float2 b = *(float2*)&Bs[(lane + 64*j)*34 + k2];
                    acc[j] += a.x*b.x; acc[j] += a.y*b.y;
                }
            }
            __syncthreads();
        }
        {
            float s = acc[0] + acc[1], s2 = acc[0]*acc[0] + acc[1]*acc[1];
#pragma unroll
            for (int o = 16; o > 0; o >>= 1) {
                s  += __shfl_xor_sync(0xffffffffu, s,  o);
                s2 += __shfl_xor_sync(0xffffffffu, s2, o);
            }
            if ((tid & 31) == 0) { red[wid*2] = s; red[wid*2+1] = s2; }
            __syncthreads();
            float ss  = red[(wid^1)*2]   + red[wid*2];
            float ss2 = red[(wid^1)*2+1] + red[wid*2+1];
            float mu = ss*(1.f/DD), var = ss2*(1.f/DD) - mu*mu;
            float rstd = rsqrtf(var + 1e-5f);
            h_s[row*130 + lane]      = fmaxf((acc[0]-mu)*rstd*gn[lane]    + bn[lane],    0.f);
            h_s[row*130 + lane + 64] = fmaxf((acc[1]-mu)*rstd*gn[lane+64] + bn[lane+64], 0.f);
        }
        __syncthreads();
        // final GEMM with prefetch
        float acc2[2] = {};
        {
            int lin0 = tid, lin1 = tid + NT;
            wreg[0] = *(const float4*)&W2[(lin0>>3)*DD + (lin0&7)*4];
            wreg[1] = *(const float4*)&W2[(lin1>>3)*DD + (lin1&7)*4];
        }
        for (int cc = 0; cc < 4; cc++) {
#pragma unroll
            for (int i = 0; i < 2; i++) {
                int lin = tid + i*NT;
                int rw = lin >> 3, c4 = lin & 7;
                float* d = &Bs[rw*34 + c4*4];
                d[0]=wreg[i].x; d[1]=wreg[i].y; d[2]=wreg[i].z; d[3]=wreg[i].w;
            }
            if (cc < 3) {
                int k0n = (cc+1) * 32;
#pragma unroll
                for (int i = 0; i < 2; i++) {
                    int lin = tid + i*NT;
                    wreg[i] = *(const float4*)&W2[(lin>>3)*DD + k0n + (lin&7)*4];
                }
            }
            int k0 = cc * 32;
            __syncthreads();
#pragma unroll 4
            for (int k2 = 0; k2 < 32; k2 += 2) {
                float2 a = *(float2*)&h_s[row*130 + k0 + k2];
#pragma unroll
                for (int j = 0; j < 2; j++) {
                    float2 b = *(float2*)&Bs[(lane + 64*j)*34 + k2];
                    acc2[j] += a.x*b.x; acc2[j] += a.y*b.y;
                }
            }
            __syncthreads();
        }
        int orow = g_inv[m0 + row];
#pragma unroll
        for (int j = 0; j < 2; j++) {
            int c = lane + 64*j;
            out[orow*DD + c] = fmaxf(acc2[j] + nodes_s[row*130 + c], 0.f);
        }
    }
}

// ------------------------------------------------------------------------
extern "C" void kernel_launch(void* const* d_in, const int* in_sizes, int n_in,
                              void* d_out, int out_size) {
    const float* agents    = (const float*)d_in[0];
    const int*   agent_ids = (const int*)  d_in[1];
    const float* lanes     = (const float*)d_in[2];
    const int*   lane_ids  = (const int*)  d_in[3];
    const float* Wq  = (const float*)d_in[4];
    const float* gq  = (const float*)d_in[5];
    const float* bq  = (const float*)d_in[6];
    const float* Wk  = (const float*)d_in[7];
    const float* gk  = (const float*)d_in[8];
    const float* bk  = (const float*)d_in[9];
    const float* Wv  = (const float*)d_in[10];
    const float* gv  = (const float*)d_in[11];
    const float* bv  = (const float*)d_in[12];
    const float* Wo1 = (const float*)d_in[13];
    const float* go1 = (const float*)d_in[14];
    const float* bo1 = (const float*)d_in[15];
    const float* Wo2 = (const float*)d_in[16];
    const float* W1  = (const float*)d_in[17];
    const float* gn  = (const float*)d_in[18];
    const float* bn  = (const float*)d_in[19];
    const float* W2  = (const float*)d_in[20];
    float* out = (float*)d_out;

    cudaFuncSetAttribute(megak, cudaFuncAttributeMaxDynamicSharedMemorySize, DYN_SMEM);

    megak<<<NB, NT, DYN_SMEM>>>(agents, agent_ids, lanes, lane_ids,
                                Wq, gq, bq, Wk, gk, bk, Wv, gv, bv,
                                Wo1, go1, bo1, Wo2, W1, gn, bn, W2, out);
}